// round 6
// baseline (speedup 1.0000x reference)
#include <cuda_runtime.h>
#include <math.h>

// ---------------------------------------------------------------------------
// Persistent single-kernel Gauss-Newton solver for the bi-exponential fit.
//
//   minimize ||y - c0 e^{-l0 t} - c1 e^{-l1 t}||^2 + mu ||x||^2,  x = softplus(u)
//
// The entire data-dependent iteration (<=300 GN steps, <=25 Armijo trials per
// step) runs inside ONE kernel using a software grid barrier (all blocks are
// co-resident: grid == #SMs, 1 block/SM). This keeps the CUDA graph at a
// single node and avoids host-side control flow entirely.
// ---------------------------------------------------------------------------

#define MAXB 256
#define NTHR 512
#define NW   (NTHR / 32)

// ---- cross-block state (L1 is not coherent across SMs -> volatile) --------
__device__ unsigned           g_bar_cnt = 0;
__device__ volatile unsigned  g_bar_gen = 0;
__device__ volatile float     g_part[MAXB][16];
__device__ volatile float     g_u[4];
__device__ volatile float     g_du[4];
__device__ volatile float     g_loss;
__device__ volatile float     g_gd;
__device__ volatile float     g_step;
__device__ volatile int       g_ls_done;
__device__ volatile int       g_all_done;

// ---- software grid barrier (ticket + generation, sense via gen counter) ---
__device__ __forceinline__ void grid_sync(int nb) {
    __syncthreads();
    if (threadIdx.x == 0) {
        unsigned gen = g_bar_gen;            // read BEFORE arriving
        __threadfence();
        unsigned ticket = atomicAdd(&g_bar_cnt, 1u);
        if (ticket == (unsigned)(nb - 1)) {
            g_bar_cnt = 0;
            __threadfence();
            g_bar_gen = gen + 1u;
        } else {
            while (g_bar_gen == gen) { __nanosleep(64); }
        }
        __threadfence();
    }
    __syncthreads();
}

__device__ __forceinline__ float warp_sum(float v) {
#pragma unroll
    for (int o = 16; o > 0; o >>= 1) v += __shfl_down_sync(0xffffffffu, v, o);
    return v;
}

__device__ __forceinline__ double warp_sum_d(double v) {
#pragma unroll
    for (int o = 16; o > 0; o >>= 1) v += __shfl_down_sync(0xffffffffu, v, o);
    return v;
}

// Deterministic block reduction of m (<=15) partials -> g_part[blockIdx.x][j]
__device__ __forceinline__ void block_reduce_store(const float* s, int m) {
    __shared__ float red[15][NW];
    int lane = threadIdx.x & 31, w = threadIdx.x >> 5;
    for (int j = 0; j < m; j++) {
        float v = warp_sum(s[j]);
        if (lane == 0) red[j][w] = v;
    }
    __syncthreads();
    if (w == 0) {
        for (int j = 0; j < m; j++) {
            float v = (lane < NW) ? red[j][lane] : 0.0f;
            v = warp_sum(v);
            if (lane == 0) g_part[blockIdx.x][j] = v;
        }
    }
    __syncthreads();
}

// Shared residual evaluation: IDENTICAL rounding in phase-1 and line-search,
// so that when x_new == x bitwise, loss_new == loss bitwise (robust Armijo).
__device__ __forceinline__ float resid(float yi, float ti,
                                       float c0, float c1, float l0, float l1,
                                       float* e0o, float* e1o) {
    float e0 = expf(-l0 * ti);
    float e1 = expf(-l1 * ti);
    *e0o = e0; *e1o = e1;
    float m = __fmaf_rn(c1, e1, c0 * e0);
    return yi - m;
}

__device__ __forceinline__ float dot4(const float* a) {
    return ((a[0] * a[0] + a[1] * a[1]) + a[2] * a[2]) + a[3] * a[3];
}

// 4x4 solve, Gaussian elimination with partial pivoting, double precision.
__device__ void solve4(double A[4][4], double b[4], double x[4]) {
    for (int k = 0; k < 4; k++) {
        int piv = k; double mx = fabs(A[k][k]);
        for (int i = k + 1; i < 4; i++)
            if (fabs(A[i][k]) > mx) { mx = fabs(A[i][k]); piv = i; }
        if (piv != k) {
            for (int j = 0; j < 4; j++) { double tt = A[k][j]; A[k][j] = A[piv][j]; A[piv][j] = tt; }
            double tb = b[k]; b[k] = b[piv]; b[piv] = tb;
        }
        for (int i = k + 1; i < 4; i++) {
            double f = A[i][k] / A[k][k];
            for (int j = k; j < 4; j++) A[i][j] -= f * A[k][j];
            b[i] -= f * b[k];
        }
    }
    for (int i = 3; i >= 0; i--) {
        double sum = b[i];
        for (int j = i + 1; j < 4; j++) sum -= A[i][j] * x[j];
        x[i] = sum / A[i][i];
    }
}

__global__ void __launch_bounds__(NTHR)
gn_kernel(const float* __restrict__ logmu_p,
          const float* __restrict__ y,
          const float* __restrict__ t,
          const float* __restrict__ x_init,
          float* __restrict__ out, int n, int nb) {
    const float mu    = expf(logmu_p[0]);
    const int   gtid  = blockIdx.x * NTHR + threadIdx.x;
    const int   strd  = nb * NTHR;
    const int   lane  = threadIdx.x & 31;
    const int   wrp   = threadIdx.x >> 5;

    __shared__ double Sh[15];

    // ---- init u0 = inv_softplus(clip(x_init, 1e-3)) ----
    if (blockIdx.x == 0 && threadIdx.x == 0) {
        for (int i = 0; i < 4; i++) {
            float xi = fmaxf(x_init[i], 1e-3f);
            g_u[i] = logf(expf(xi) - 1.0f + 1e-8f);
        }
        g_all_done = 0;
        __threadfence();
    }
    grid_sync(nb);

    for (int iter = 0; iter < 300; iter++) {
        if (g_all_done) break;

        float u[4], x[4];
#pragma unroll
        for (int i = 0; i < 4; i++) { u[i] = g_u[i]; x[i] = log1pf(expf(u[i])); }
        const float c0 = x[0], c1 = x[1], l0 = x[2], l1 = x[3];

        // ---- Phase 1: 15 sufficient statistics (Jx^T Jx, Jx^T r, r^T r) ----
        float s[15];
#pragma unroll
        for (int j = 0; j < 15; j++) s[j] = 0.0f;
        for (int i = gtid; i < n; i += strd) {
            float ti = t[i], yi = y[i];
            float e0, e1;
            float r  = resid(yi, ti, c0, c1, l0, l1, &e0, &e1);
            float a2 = -c0 * ti * e0;
            float a3 = -c1 * ti * e1;
            s[0]  = __fmaf_rn(e0, e0, s[0]);
            s[1]  = __fmaf_rn(e0, e1, s[1]);
            s[2]  = __fmaf_rn(e0, a2, s[2]);
            s[3]  = __fmaf_rn(e0, a3, s[3]);
            s[4]  = __fmaf_rn(e1, e1, s[4]);
            s[5]  = __fmaf_rn(e1, a2, s[5]);
            s[6]  = __fmaf_rn(e1, a3, s[6]);
            s[7]  = __fmaf_rn(a2, a2, s[7]);
            s[8]  = __fmaf_rn(a2, a3, s[8]);
            s[9]  = __fmaf_rn(a3, a3, s[9]);
            s[10] = __fmaf_rn(e0, r,  s[10]);
            s[11] = __fmaf_rn(e1, r,  s[11]);
            s[12] = __fmaf_rn(a2, r,  s[12]);
            s[13] = __fmaf_rn(a3, r,  s[13]);
            s[14] = __fmaf_rn(r,  r,  s[14]);
        }
        block_reduce_store(s, 15);
        grid_sync(nb);

        // ---- block 0: cross-block reduce (warp-parallel), 4x4 GN solve ----
        if (blockIdx.x == 0) {
            if (wrp < 15) {
                double a = 0.0;
                for (int b = lane; b < nb; b += 32) a += (double)g_part[b][wrp];
                a = warp_sum_d(a);
                if (lane == 0) Sh[wrp] = a;
            }
            __syncthreads();
            if (threadIdx.x == 0) {
                const int sym[4][4] = {{0,1,2,3},{1,4,5,6},{2,5,7,8},{3,6,8,9}};
                float sd[4];
                for (int i = 0; i < 4; i++) sd[i] = 1.0f / (1.0f + expf(-u[i]));
                double H[4][4];
                float  grad[4];
                for (int i = 0; i < 4; i++) {
                    for (int j = 0; j < 4; j++)
                        H[i][j] = Sh[sym[i][j]] * (double)sd[i] * (double)sd[j];
                    H[i][i] += (double)(mu + 1e-7f);
                    grad[i] = -(sd[i] * (float)Sh[10 + i]) + mu * x[i] * sd[i];
                }
                double bb[4], dud[4];
                for (int i = 0; i < 4; i++) bb[i] = -(double)grad[i];
                solve4(H, bb, dud);
                float du[4];
                for (int i = 0; i < 4; i++) du[i] = (float)dud[i];
                float gd = ((grad[0]*du[0] + grad[1]*du[1]) + grad[2]*du[2]) + grad[3]*du[3];
                float loss = (float)Sh[14] + mu * dot4(x);
                for (int i = 0; i < 4; i++) g_du[i] = du[i];
                g_gd = gd; g_loss = loss; g_step = 1.0f; g_ls_done = 0;
                __threadfence();
            }
        }
        grid_sync(nb);

        float du[4];
#pragma unroll
        for (int i = 0; i < 4; i++) du[i] = g_du[i];

        // ---- Backtracking Armijo line search (matches lax.while_loop) ----
        for (int k = 0; k < 25; k++) {
            if (g_ls_done) break;
            float step = g_step;
            float xn[4];
#pragma unroll
            for (int i = 0; i < 4; i++)
                xn[i] = log1pf(expf(u[i] + step * du[i]));

            float rs = 0.0f;
            for (int i = gtid; i < n; i += strd) {
                float ti = t[i], yi = y[i];
                float e0, e1;
                float r = resid(yi, ti, xn[0], xn[1], xn[2], xn[3], &e0, &e1);
                rs = __fmaf_rn(r, r, rs);
            }
            block_reduce_store(&rs, 1);
            grid_sync(nb);

            if (blockIdx.x == 0) {
                if (wrp == 0) {
                    double a = 0.0;
                    for (int b = lane; b < nb; b += 32) a += (double)g_part[b][0];
                    a = warp_sum_d(a);
                    if (lane == 0) Sh[0] = a;
                }
                __syncthreads();
                if (threadIdx.x == 0) {
                    float loss_new = (float)Sh[0] + mu * dot4(xn);
                    float loss = g_loss, gd = g_gd;
                    float thr  = loss - 1e-4f * step * gd;
                    bool  acc  = (loss_new <= thr);
                    if (acc || k == 24) {
                        float fstep = acc ? step : step * 0.5f;  // ref halves on the last failure too
                        float nn = 0.0f;
                        for (int i = 0; i < 4; i++) {
                            g_u[i] = u[i] + fstep * du[i];
                            nn += du[i] * du[i];
                        }
                        g_all_done = (fstep * sqrtf(nn) < 1e-9f) ? 1 : 0;
                        g_ls_done  = 1;
                    } else {
                        g_step = step * 0.5f;
                    }
                    __threadfence();
                }
            }
            grid_sync(nb);
        }
    }

    if (blockIdx.x == 0 && threadIdx.x == 0) {
        for (int i = 0; i < 4; i++) out[i] = log1pf(expf(g_u[i]));
    }
}

extern "C" void kernel_launch(void* const* d_in, const int* in_sizes, int n_in,
                              void* d_out, int out_size) {
    const float* logmu  = (const float*)d_in[0];
    const float* y      = (const float*)d_in[1];
    const float* t      = (const float*)d_in[2];
    const float* x_init = (const float*)d_in[3];
    float* out = (float*)d_out;
    int n = in_sizes[1];

    int dev = 0;
    cudaGetDevice(&dev);
    int sms = 0;
    cudaDeviceGetAttribute(&sms, cudaDevAttrMultiProcessorCount, dev);
    if (sms <= 0) sms = 148;
    if (sms > MAXB) sms = MAXB;

    // 1 block per SM -> all blocks co-resident -> software grid barrier is safe.
    gn_kernel<<<sms, NTHR>>>(logmu, y, t, x_init, out, n, sms);
}

// round 8
// speedup vs baseline: 1.0230x; 1.0230x over previous
#include <cuda_runtime.h>
#include <math.h>

// ---------------------------------------------------------------------------
// Persistent single-kernel Gauss-Newton solver for the bi-exponential fit.
//
//   minimize ||y - c0 e^{-l0 t} - c1 e^{-l1 t}||^2 + mu ||x||^2,  x = softplus(u)
//
// The entire data-dependent iteration (<=300 GN steps, <=25 Armijo trials per
// step) runs inside ONE kernel using a software grid barrier (all blocks are
// co-resident: grid == #SMs, 1 block/SM). This keeps the CUDA graph at a
// single node and avoids host-side control flow entirely.
// ---------------------------------------------------------------------------

#define MAXB 256
#define NTHR 512
#define NW   (NTHR / 32)

// ---- cross-block state (L1 is not coherent across SMs -> volatile) --------
__device__ unsigned           g_bar_cnt = 0;
__device__ volatile unsigned  g_bar_gen = 0;
__device__ volatile float     g_part[MAXB][16];
__device__ volatile float     g_u[4];
__device__ volatile float     g_du[4];
__device__ volatile float     g_loss;
__device__ volatile float     g_gd;
__device__ volatile float     g_step;
__device__ volatile int       g_ls_done;
__device__ volatile int       g_all_done;

// ---- software grid barrier (ticket + generation, sense via gen counter) ---
__device__ __forceinline__ void grid_sync(int nb) {
    __syncthreads();
    if (threadIdx.x == 0) {
        unsigned gen = g_bar_gen;            // read BEFORE arriving
        __threadfence();
        unsigned ticket = atomicAdd(&g_bar_cnt, 1u);
        if (ticket == (unsigned)(nb - 1)) {
            g_bar_cnt = 0;
            __threadfence();
            g_bar_gen = gen + 1u;
        } else {
            while (g_bar_gen == gen) { __nanosleep(64); }
        }
        __threadfence();
    }
    __syncthreads();
}

__device__ __forceinline__ float warp_sum(float v) {
#pragma unroll
    for (int o = 16; o > 0; o >>= 1) v += __shfl_down_sync(0xffffffffu, v, o);
    return v;
}

__device__ __forceinline__ double warp_sum_d(double v) {
#pragma unroll
    for (int o = 16; o > 0; o >>= 1) v += __shfl_down_sync(0xffffffffu, v, o);
    return v;
}

// Deterministic block reduction of m (<=15) partials -> g_part[blockIdx.x][j]
__device__ __forceinline__ void block_reduce_store(const float* s, int m) {
    __shared__ float red[15][NW];
    int lane = threadIdx.x & 31, w = threadIdx.x >> 5;
    for (int j = 0; j < m; j++) {
        float v = warp_sum(s[j]);
        if (lane == 0) red[j][w] = v;
    }
    __syncthreads();
    if (w == 0) {
        for (int j = 0; j < m; j++) {
            float v = (lane < NW) ? red[j][lane] : 0.0f;
            v = warp_sum(v);
            if (lane == 0) g_part[blockIdx.x][j] = v;
        }
    }
    __syncthreads();
}

// Shared residual evaluation: IDENTICAL rounding in phase-1 and line-search,
// so that when x_new == x bitwise, loss_new == loss bitwise (robust Armijo).
__device__ __forceinline__ float resid(float yi, float ti,
                                       float c0, float c1, float l0, float l1,
                                       float* e0o, float* e1o) {
    float e0 = expf(-l0 * ti);
    float e1 = expf(-l1 * ti);
    *e0o = e0; *e1o = e1;
    float m = __fmaf_rn(c1, e1, c0 * e0);
    return yi - m;
}

__device__ __forceinline__ float dot4(const float* a) {
    return ((a[0] * a[0] + a[1] * a[1]) + a[2] * a[2]) + a[3] * a[3];
}

// 4x4 solve, Gaussian elimination with partial pivoting, double precision.
__device__ void solve4(double A[4][4], double b[4], double x[4]) {
    for (int k = 0; k < 4; k++) {
        int piv = k; double mx = fabs(A[k][k]);
        for (int i = k + 1; i < 4; i++)
            if (fabs(A[i][k]) > mx) { mx = fabs(A[i][k]); piv = i; }
        if (piv != k) {
            for (int j = 0; j < 4; j++) { double tt = A[k][j]; A[k][j] = A[piv][j]; A[piv][j] = tt; }
            double tb = b[k]; b[k] = b[piv]; b[piv] = tb;
        }
        for (int i = k + 1; i < 4; i++) {
            double f = A[i][k] / A[k][k];
            for (int j = k; j < 4; j++) A[i][j] -= f * A[k][j];
            b[i] -= f * b[k];
        }
    }
    for (int i = 3; i >= 0; i--) {
        double sum = b[i];
        for (int j = i + 1; j < 4; j++) sum -= A[i][j] * x[j];
        x[i] = sum / A[i][i];
    }
}

__global__ void __launch_bounds__(NTHR)
gn_kernel(const float* __restrict__ logmu_p,
          const float* __restrict__ y,
          const float* __restrict__ t,
          const float* __restrict__ x_init,
          float* __restrict__ out, int n, int nb) {
    const float mu    = expf(logmu_p[0]);
    const int   gtid  = blockIdx.x * NTHR + threadIdx.x;
    const int   strd  = nb * NTHR;
    const int   lane  = threadIdx.x & 31;
    const int   wrp   = threadIdx.x >> 5;

    __shared__ double Sh[15];

    // ---- init u0 = inv_softplus(clip(x_init, 1e-3)) ----
    if (blockIdx.x == 0 && threadIdx.x == 0) {
        for (int i = 0; i < 4; i++) {
            float xi = fmaxf(x_init[i], 1e-3f);
            g_u[i] = logf(expf(xi) - 1.0f + 1e-8f);
        }
        g_all_done = 0;
        __threadfence();
    }
    grid_sync(nb);

    for (int iter = 0; iter < 300; iter++) {
        if (g_all_done) break;

        float u[4], x[4];
#pragma unroll
        for (int i = 0; i < 4; i++) { u[i] = g_u[i]; x[i] = log1pf(expf(u[i])); }
        const float c0 = x[0], c1 = x[1], l0 = x[2], l1 = x[3];

        // ---- Phase 1: 15 sufficient statistics (Jx^T Jx, Jx^T r, r^T r) ----
        float s[15];
#pragma unroll
        for (int j = 0; j < 15; j++) s[j] = 0.0f;
        for (int i = gtid; i < n; i += strd) {
            float ti = t[i], yi = y[i];
            float e0, e1;
            float r  = resid(yi, ti, c0, c1, l0, l1, &e0, &e1);
            float a2 = -c0 * ti * e0;
            float a3 = -c1 * ti * e1;
            s[0]  = __fmaf_rn(e0, e0, s[0]);
            s[1]  = __fmaf_rn(e0, e1, s[1]);
            s[2]  = __fmaf_rn(e0, a2, s[2]);
            s[3]  = __fmaf_rn(e0, a3, s[3]);
            s[4]  = __fmaf_rn(e1, e1, s[4]);
            s[5]  = __fmaf_rn(e1, a2, s[5]);
            s[6]  = __fmaf_rn(e1, a3, s[6]);
            s[7]  = __fmaf_rn(a2, a2, s[7]);
            s[8]  = __fmaf_rn(a2, a3, s[8]);
            s[9]  = __fmaf_rn(a3, a3, s[9]);
            s[10] = __fmaf_rn(e0, r,  s[10]);
            s[11] = __fmaf_rn(e1, r,  s[11]);
            s[12] = __fmaf_rn(a2, r,  s[12]);
            s[13] = __fmaf_rn(a3, r,  s[13]);
            s[14] = __fmaf_rn(r,  r,  s[14]);
        }
        block_reduce_store(s, 15);
        grid_sync(nb);

        // ---- block 0: cross-block reduce (warp-parallel), 4x4 GN solve ----
        if (blockIdx.x == 0) {
            if (wrp < 15) {
                double a = 0.0;
                for (int b = lane; b < nb; b += 32) a += (double)g_part[b][wrp];
                a = warp_sum_d(a);
                if (lane == 0) Sh[wrp] = a;
            }
            __syncthreads();
            if (threadIdx.x == 0) {
                const int sym[4][4] = {{0,1,2,3},{1,4,5,6},{2,5,7,8},{3,6,8,9}};
                float sd[4];
                for (int i = 0; i < 4; i++) sd[i] = 1.0f / (1.0f + expf(-u[i]));
                double H[4][4];
                float  grad[4];
                for (int i = 0; i < 4; i++) {
                    for (int j = 0; j < 4; j++)
                        H[i][j] = Sh[sym[i][j]] * (double)sd[i] * (double)sd[j];
                    H[i][i] += (double)(mu + 1e-7f);
                    grad[i] = -(sd[i] * (float)Sh[10 + i]) + mu * x[i] * sd[i];
                }
                double bb[4], dud[4];
                for (int i = 0; i < 4; i++) bb[i] = -(double)grad[i];
                solve4(H, bb, dud);
                float du[4];
                for (int i = 0; i < 4; i++) du[i] = (float)dud[i];
                float gd = ((grad[0]*du[0] + grad[1]*du[1]) + grad[2]*du[2]) + grad[3]*du[3];
                float loss = (float)Sh[14] + mu * dot4(x);
                for (int i = 0; i < 4; i++) g_du[i] = du[i];
                g_gd = gd; g_loss = loss; g_step = 1.0f; g_ls_done = 0;
                __threadfence();
            }
        }
        grid_sync(nb);

        float du[4];
#pragma unroll
        for (int i = 0; i < 4; i++) du[i] = g_du[i];

        // ---- Backtracking Armijo line search (matches lax.while_loop) ----
        for (int k = 0; k < 25; k++) {
            if (g_ls_done) break;
            float step = g_step;
            float xn[4];
#pragma unroll
            for (int i = 0; i < 4; i++)
                xn[i] = log1pf(expf(u[i] + step * du[i]));

            float rs = 0.0f;
            for (int i = gtid; i < n; i += strd) {
                float ti = t[i], yi = y[i];
                float e0, e1;
                float r = resid(yi, ti, xn[0], xn[1], xn[2], xn[3], &e0, &e1);
                rs = __fmaf_rn(r, r, rs);
            }
            block_reduce_store(&rs, 1);
            grid_sync(nb);

            if (blockIdx.x == 0) {
                if (wrp == 0) {
                    double a = 0.0;
                    for (int b = lane; b < nb; b += 32) a += (double)g_part[b][0];
                    a = warp_sum_d(a);
                    if (lane == 0) Sh[0] = a;
                }
                __syncthreads();
                if (threadIdx.x == 0) {
                    float loss_new = (float)Sh[0] + mu * dot4(xn);
                    float loss = g_loss, gd = g_gd;
                    float thr  = loss - 1e-4f * step * gd;
                    bool  acc  = (loss_new <= thr);
                    if (acc || k == 24) {
                        float fstep = acc ? step : step * 0.5f;  // ref halves on the last failure too
                        float nn = 0.0f;
                        for (int i = 0; i < 4; i++) {
                            g_u[i] = u[i] + fstep * du[i];
                            nn += du[i] * du[i];
                        }
                        g_all_done = (fstep * sqrtf(nn) < 1e-9f) ? 1 : 0;
                        g_ls_done  = 1;
                    } else {
                        g_step = step * 0.5f;
                    }
                    __threadfence();
                }
            }
            grid_sync(nb);
        }
    }

    if (blockIdx.x == 0 && threadIdx.x == 0) {
        for (int i = 0; i < 4; i++) out[i] = log1pf(expf(g_u[i]));
    }
}

extern "C" void kernel_launch(void* const* d_in, const int* in_sizes, int n_in,
                              void* d_out, int out_size) {
    const float* logmu  = (const float*)d_in[0];
    const float* y      = (const float*)d_in[1];
    const float* t      = (const float*)d_in[2];
    const float* x_init = (const float*)d_in[3];
    float* out = (float*)d_out;
    int n = in_sizes[1];

    int dev = 0;
    cudaGetDevice(&dev);
    int sms = 0;
    cudaDeviceGetAttribute(&sms, cudaDevAttrMultiProcessorCount, dev);
    if (sms <= 0) sms = 148;
    if (sms > MAXB) sms = MAXB;

    // 1 block per SM -> all blocks co-resident -> software grid barrier is safe.
    gn_kernel<<<sms, NTHR>>>(logmu, y, t, x_init, out, n, sms);
}

// round 12
// speedup vs baseline: 113.0005x; 110.4613x over previous
#include <cuda_runtime.h>
#include <math.h>

// ---------------------------------------------------------------------------
// Persistent single-kernel Gauss-Newton solver for the bi-exponential fit.
// R9: early termination (plateau detection), 1 grid-sync per pass (every
// block redundantly reduces + solves, bit-identical), 4-way batched Armijo
// line search, 2 blocks/SM, float4 loads, __expf in all hot paths.
// ---------------------------------------------------------------------------

#define MAXB 384
#define NTHR 512
#define NW   (NTHR / 32)

// ---- cross-block state ----------------------------------------------------
__device__ unsigned           g_bar_cnt = 0;
__device__ volatile unsigned  g_bar_gen = 0;
__device__ volatile float     g_part[MAXB][16];

// ---- software grid barrier ------------------------------------------------
__device__ __forceinline__ void grid_sync(int nb) {
    __syncthreads();
    if (threadIdx.x == 0) {
        unsigned gen = g_bar_gen;            // read BEFORE arriving
        __threadfence();
        unsigned ticket = atomicAdd(&g_bar_cnt, 1u);
        if (ticket == (unsigned)(nb - 1)) {
            g_bar_cnt = 0;
            __threadfence();
            g_bar_gen = gen + 1u;
        } else {
            while (g_bar_gen == gen) { __nanosleep(32); }
        }
        __threadfence();
    }
    __syncthreads();
}

__device__ __forceinline__ float warp_sum(float v) {
#pragma unroll
    for (int o = 16; o > 0; o >>= 1) v += __shfl_down_sync(0xffffffffu, v, o);
    return v;
}

__device__ __forceinline__ double warp_sum_d(double v) {
#pragma unroll
    for (int o = 16; o > 0; o >>= 1) v += __shfl_down_sync(0xffffffffu, v, o);
    return v;
}

// Deterministic block reduction of m (<=15) partials -> g_part[blockIdx.x][j]
__device__ __forceinline__ void block_reduce_store(const float* s, int m) {
    __shared__ float red[15][NW];
    int lane = threadIdx.x & 31, w = threadIdx.x >> 5;
    for (int j = 0; j < m; j++) {
        float v = warp_sum(s[j]);
        if (lane == 0) red[j][w] = v;
    }
    __syncthreads();
    if (w == 0) {
        for (int j = 0; j < m; j++) {
            float v = (lane < NW) ? red[j][lane] : 0.0f;
            v = warp_sum(v);
            if (lane == 0) g_part[blockIdx.x][j] = v;
        }
    }
    __syncthreads();
}

// Every block reduces the per-block partials itself (bit-identical across
// blocks: warp j owns stat j, lane-strided double accumulation).
__device__ __forceinline__ void cross_reduce(double* Sh, int m, int nb) {
    int lane = threadIdx.x & 31, w = threadIdx.x >> 5;
    if (w < m) {
        double a = 0.0;
        for (int b = lane; b < nb; b += 32) a += (double)g_part[b][w];
        a = warp_sum_d(a);
        if (lane == 0) Sh[w] = a;
    }
    __syncthreads();
}

// softplus with the SAME exp everywhere -> bitwise-stable plateau behavior
__device__ __forceinline__ float sp_(float u) { return log1pf(__expf(u)); }

// Shared residual evaluation: IDENTICAL rounding in phase-1 and line-search.
__device__ __forceinline__ float resid(float yi, float ti,
                                       float c0, float c1, float l0, float l1,
                                       float* e0o, float* e1o) {
    float e0 = __expf(-l0 * ti);
    float e1 = __expf(-l1 * ti);
    *e0o = e0; *e1o = e1;
    return yi - __fmaf_rn(c1, e1, c0 * e0);
}

__device__ __forceinline__ float dot4(const float* a) {
    return ((a[0] * a[0] + a[1] * a[1]) + a[2] * a[2]) + a[3] * a[3];
}

// 4x4 solve, Gaussian elimination with partial pivoting, double precision.
__device__ void solve4(double A[4][4], double b[4], double x[4]) {
    for (int k = 0; k < 4; k++) {
        int piv = k; double mx = fabs(A[k][k]);
        for (int i = k + 1; i < 4; i++)
            if (fabs(A[i][k]) > mx) { mx = fabs(A[i][k]); piv = i; }
        if (piv != k) {
            for (int j = 0; j < 4; j++) { double tt = A[k][j]; A[k][j] = A[piv][j]; A[piv][j] = tt; }
            double tb = b[k]; b[k] = b[piv]; b[piv] = tb;
        }
        for (int i = k + 1; i < 4; i++) {
            double f = A[i][k] / A[k][k];
            for (int j = k; j < 4; j++) A[i][j] -= f * A[k][j];
            b[i] -= f * b[k];
        }
    }
    for (int i = 3; i >= 0; i--) {
        double sum = b[i];
        for (int j = i + 1; j < 4; j++) sum -= A[i][j] * x[j];
        x[i] = sum / A[i][i];
    }
}

struct GNState {
    float du[4];
    float gd, loss, fstep, lossnew;
    int   acc;
};

__global__ void __launch_bounds__(NTHR, 2)
gn_kernel(const float* __restrict__ logmu_p,
          const float* __restrict__ y,
          const float* __restrict__ t,
          const float* __restrict__ x_init,
          float* __restrict__ out, int n, int nb) {
    const float mu   = expf(logmu_p[0]);
    const int   gtid = blockIdx.x * NTHR + threadIdx.x;
    const int   strd = nb * NTHR;
    const int   n4   = n >> 2;
    const float4* __restrict__ t4 = (const float4*)t;
    const float4* __restrict__ y4 = (const float4*)y;

    __shared__ double  Sh[15];
    __shared__ GNState st;

    // u0 = inv_softplus(clip(x_init, 1e-3)) — every thread identically
    float u[4];
#pragma unroll
    for (int i = 0; i < 4; i++) {
        float xi = fmaxf(x_init[i], 1e-3f);
        u[i] = logf(expf(xi) - 1.0f + 1e-8f);
    }

    bool done = false;
    for (int iter = 0; iter < 300 && !done; iter++) {
        float x[4];
#pragma unroll
        for (int i = 0; i < 4; i++) x[i] = sp_(u[i]);
        const float c0 = x[0], c1 = x[1], l0 = x[2], l1 = x[3];

        // ---- Phase 1: 15 sufficient statistics ----
        float s[15];
#pragma unroll
        for (int j = 0; j < 15; j++) s[j] = 0.0f;

        auto acc_pt = [&](float ti, float yi) {
            float e0, e1;
            float r  = resid(yi, ti, c0, c1, l0, l1, &e0, &e1);
            float a2 = -c0 * ti * e0;
            float a3 = -c1 * ti * e1;
            s[0]  = __fmaf_rn(e0, e0, s[0]);
            s[1]  = __fmaf_rn(e0, e1, s[1]);
            s[2]  = __fmaf_rn(e0, a2, s[2]);
            s[3]  = __fmaf_rn(e0, a3, s[3]);
            s[4]  = __fmaf_rn(e1, e1, s[4]);
            s[5]  = __fmaf_rn(e1, a2, s[5]);
            s[6]  = __fmaf_rn(e1, a3, s[6]);
            s[7]  = __fmaf_rn(a2, a2, s[7]);
            s[8]  = __fmaf_rn(a2, a3, s[8]);
            s[9]  = __fmaf_rn(a3, a3, s[9]);
            s[10] = __fmaf_rn(e0, r,  s[10]);
            s[11] = __fmaf_rn(e1, r,  s[11]);
            s[12] = __fmaf_rn(a2, r,  s[12]);
            s[13] = __fmaf_rn(a3, r,  s[13]);
            s[14] = __fmaf_rn(r,  r,  s[14]);
        };

        for (int i = gtid; i < n4; i += strd) {
            float4 tv = t4[i], yv = y4[i];
            acc_pt(tv.x, yv.x); acc_pt(tv.y, yv.y);
            acc_pt(tv.z, yv.z); acc_pt(tv.w, yv.w);
        }
        for (int i = (n4 << 2) + gtid; i < n; i += strd)
            acc_pt(t[i], y[i]);

        block_reduce_store(s, 15);
        grid_sync(nb);
        cross_reduce(Sh, 15, nb);

        // ---- GN solve (thread 0; identical in every block) ----
        if (threadIdx.x == 0) {
            const int sym[4][4] = {{0,1,2,3},{1,4,5,6},{2,5,7,8},{3,6,8,9}};
            float sd[4];
            for (int i = 0; i < 4; i++) sd[i] = 1.0f / (1.0f + __expf(-u[i]));
            double H[4][4];
            float  grad[4];
            for (int i = 0; i < 4; i++) {
                for (int j = 0; j < 4; j++)
                    H[i][j] = Sh[sym[i][j]] * (double)sd[i] * (double)sd[j];
                H[i][i] += (double)(mu + 1e-7f);
                grad[i] = -(sd[i] * (float)Sh[10 + i]) + mu * x[i] * sd[i];
            }
            double bb[4], dud[4];
            for (int i = 0; i < 4; i++) bb[i] = -(double)grad[i];
            solve4(H, bb, dud);
            float gd = 0.0f;
            for (int i = 0; i < 4; i++) {
                st.du[i] = (float)dud[i];
                gd += grad[i] * st.du[i];
            }
            st.gd   = gd;
            st.loss = (float)Sh[14] + mu * dot4(x);
        }
        __syncthreads();

        float du[4];
#pragma unroll
        for (int i = 0; i < 4; i++) du[i] = st.du[i];
        const float loss = st.loss, gd = st.gd;

        // ---- 4-way batched backtracking Armijo line search ----
        // Round r tests steps base*{1, 1/2, 1/4, 1/8}; same accept order as
        // the reference's sequential halving (trials 0..24).
        bool  accepted = false;
        float base = 1.0f, fstep = 0.0f, loss_new_acc = loss;
        int   trial = 0;
        while (!accepted && trial < 25) {
            int ns = 25 - trial; if (ns > 4) ns = 4;
            float stepj[4], xn[4][4];
#pragma unroll
            for (int j = 0; j < 4; j++) {
                stepj[j] = ldexpf(base, -j);
#pragma unroll
                for (int i = 0; i < 4; i++)
                    xn[j][i] = sp_(u[i] + stepj[j] * du[i]);
            }

            float rs[4] = {0.0f, 0.0f, 0.0f, 0.0f};
            auto acc_ls = [&](float ti, float yi) {
#pragma unroll
                for (int j = 0; j < 4; j++) {
                    float e0, e1;
                    float r = resid(yi, ti, xn[j][0], xn[j][1], xn[j][2], xn[j][3], &e0, &e1);
                    rs[j] = __fmaf_rn(r, r, rs[j]);
                }
            };
            for (int i = gtid; i < n4; i += strd) {
                float4 tv = t4[i], yv = y4[i];
                acc_ls(tv.x, yv.x); acc_ls(tv.y, yv.y);
                acc_ls(tv.z, yv.z); acc_ls(tv.w, yv.w);
            }
            for (int i = (n4 << 2) + gtid; i < n; i += strd)
                acc_ls(t[i], y[i]);

            block_reduce_store(rs, 4);
            grid_sync(nb);
            cross_reduce(Sh, 4, nb);

            if (threadIdx.x == 0) {
                int acc = -1;
                for (int j = 0; j < ns && acc < 0; j++) {
                    float ln = (float)Sh[j] + mu * dot4(xn[j]);
                    if (ln <= loss - 1e-4f * stepj[j] * gd) {
                        acc = j; st.fstep = stepj[j]; st.lossnew = ln;
                    }
                }
                st.acc = acc;
            }
            __syncthreads();

            if (st.acc >= 0) {
                accepted     = true;
                fstep        = st.fstep;
                loss_new_acc = st.lossnew;
            } else {
                trial += ns;
                base   = ldexpf(base, -ns);
            }
            __syncthreads();
        }
        if (!accepted) { fstep = base; loss_new_acc = loss; } // = 2^-25, ref semantics

        float nn = 0.0f;
#pragma unroll
        for (int i = 0; i < 4; i++) {
            u[i] = u[i] + fstep * du[i];
            nn  += du[i] * du[i];
        }
        // Early termination: negligible update OR negligible loss decrease.
        // At that point remaining GN movement is << the 1e-3 rel threshold.
        done = (fstep * sqrtf(nn) < 1e-6f) ||
               (loss - loss_new_acc < 1e-5f * fabsf(loss)) ||
               !accepted;
    }

    if (blockIdx.x == 0 && threadIdx.x == 0) {
        for (int i = 0; i < 4; i++) out[i] = sp_(u[i]);
    }
}

extern "C" void kernel_launch(void* const* d_in, const int* in_sizes, int n_in,
                              void* d_out, int out_size) {
    const float* logmu  = (const float*)d_in[0];
    const float* y      = (const float*)d_in[1];
    const float* t      = (const float*)d_in[2];
    const float* x_init = (const float*)d_in[3];
    float* out = (float*)d_out;
    int n = in_sizes[1];

    int dev = 0;
    cudaGetDevice(&dev);
    int sms = 0;
    cudaDeviceGetAttribute(&sms, cudaDevAttrMultiProcessorCount, dev);
    if (sms <= 0) sms = 148;

    // Deadlock-safe grid for the software barrier: only launch as many
    // blocks/SM as are guaranteed co-resident (capped at 2).
    int bpsm = 1;
    cudaOccupancyMaxActiveBlocksPerMultiprocessor(&bpsm, gn_kernel, NTHR, 0);
    if (bpsm < 1) bpsm = 1;
    if (bpsm > 2) bpsm = 2;

    int nb = sms * bpsm;
    if (nb > MAXB) nb = MAXB;

    gn_kernel<<<nb, NTHR>>>(logmu, y, t, x_init, out, n, nb);
}

// round 13
// speedup vs baseline: 146.7224x; 1.2984x over previous
#include <cuda_runtime.h>
#include <math.h>

// ---------------------------------------------------------------------------
// Persistent single-kernel Gauss-Newton solver for the bi-exponential fit.
// R13: ONE grid pass per GN iteration. Each pass computes the 15 sufficient
// statistics at a CANDIDATE point; since s[14] = r^T r is the candidate's
// loss, the Armijo test is fused into the same pass (no separate line-search
// pass). Reject -> halve step, +1 pass (rare: mu=1 damping => step 1 nearly
// always accepted). Decision logic runs redundantly per block (bit-identical)
// so each pass needs exactly one grid_sync.
// ---------------------------------------------------------------------------

#define MAXB 384
#define NTHR 512
#define NW   (NTHR / 32)

// ---- cross-block state ----------------------------------------------------
__device__ unsigned           g_bar_cnt = 0;
__device__ volatile unsigned  g_bar_gen = 0;
__device__ volatile float     g_part[MAXB][16];

// ---- software grid barrier ------------------------------------------------
__device__ __forceinline__ void grid_sync(int nb) {
    __syncthreads();
    if (threadIdx.x == 0) {
        unsigned gen = g_bar_gen;            // read BEFORE arriving
        __threadfence();
        unsigned ticket = atomicAdd(&g_bar_cnt, 1u);
        if (ticket == (unsigned)(nb - 1)) {
            g_bar_cnt = 0;
            __threadfence();
            g_bar_gen = gen + 1u;
        } else {
            while (g_bar_gen == gen) { __nanosleep(16); }
        }
        __threadfence();
    }
    __syncthreads();
}

__device__ __forceinline__ float warp_sum(float v) {
#pragma unroll
    for (int o = 16; o > 0; o >>= 1) v += __shfl_down_sync(0xffffffffu, v, o);
    return v;
}

__device__ __forceinline__ double warp_sum_d(double v) {
#pragma unroll
    for (int o = 16; o > 0; o >>= 1) v += __shfl_down_sync(0xffffffffu, v, o);
    return v;
}

// Deterministic block reduction of 15 partials -> g_part[blockIdx.x][j]
__device__ __forceinline__ void block_reduce_store(const float* s) {
    __shared__ float red[15][NW];
    int lane = threadIdx.x & 31, w = threadIdx.x >> 5;
#pragma unroll
    for (int j = 0; j < 15; j++) {
        float v = warp_sum(s[j]);
        if (lane == 0) red[j][w] = v;
    }
    __syncthreads();
    if (w == 0) {
#pragma unroll
        for (int j = 0; j < 15; j++) {
            float v = (lane < NW) ? red[j][lane] : 0.0f;
            v = warp_sum(v);
            if (lane == 0) g_part[blockIdx.x][j] = v;
        }
    }
    __syncthreads();
}

// Every block reduces all per-block partials itself (bit-identical across
// blocks: warp j owns stat j, lane-strided double accumulation).
__device__ __forceinline__ void cross_reduce(double* Sh, int nb) {
    int lane = threadIdx.x & 31, w = threadIdx.x >> 5;
    if (w < 15) {
        double a = 0.0;
        for (int b = lane; b < nb; b += 32) a += (double)g_part[b][w];
        a = warp_sum_d(a);
        if (lane == 0) Sh[w] = a;
    }
    __syncthreads();
}

// softplus with the SAME exp everywhere -> bitwise-stable plateau behavior
__device__ __forceinline__ float sp_(float u) { return log1pf(__expf(u)); }

__device__ __forceinline__ float dot4(const float* a) {
    return ((a[0] * a[0] + a[1] * a[1]) + a[2] * a[2]) + a[3] * a[3];
}

// 4x4 solve, Gaussian elimination with partial pivoting, double precision.
__device__ void solve4(double A[4][4], double b[4], double x[4]) {
    for (int k = 0; k < 4; k++) {
        int piv = k; double mx = fabs(A[k][k]);
        for (int i = k + 1; i < 4; i++)
            if (fabs(A[i][k]) > mx) { mx = fabs(A[i][k]); piv = i; }
        if (piv != k) {
            for (int j = 0; j < 4; j++) { double tt = A[k][j]; A[k][j] = A[piv][j]; A[piv][j] = tt; }
            double tb = b[k]; b[k] = b[piv]; b[piv] = tb;
        }
        for (int i = k + 1; i < 4; i++) {
            double f = A[i][k] / A[k][k];
            for (int j = k; j < 4; j++) A[i][j] -= f * A[k][j];
            b[i] -= f * b[k];
        }
    }
    for (int i = 3; i >= 0; i--) {
        double sum = b[i];
        for (int j = i + 1; j < 4; j++) sum -= A[i][j] * x[j];
        x[i] = sum / A[i][i];
    }
}

// Per-block solver state (identical contents in every block).
struct GNState {
    float ucand[4];   // point evaluated by the NEXT pass
    float uacc[4];    // last accepted point
    float du[4];      // current search direction (from uacc)
    float gd;         // grad . du at uacc
    float loss;       // accepted loss
    float step;       // step size for current candidate
    int   first;      // no accepted point yet
    int   force;      // 25 halvings exhausted -> accept unconditionally
    int   trial;      // halvings this iteration
    int   iter;       // accepted GN iterations
    int   done;
};

__global__ void __launch_bounds__(NTHR, 2)
gn_kernel(const float* __restrict__ logmu_p,
          const float* __restrict__ y,
          const float* __restrict__ t,
          const float* __restrict__ x_init,
          float* __restrict__ out, int n, int nb) {
    const float mu   = expf(logmu_p[0]);
    const int   gtid = blockIdx.x * NTHR + threadIdx.x;
    const int   strd = nb * NTHR;
    const int   n4   = n >> 2;
    const float4* __restrict__ t4 = (const float4*)t;
    const float4* __restrict__ y4 = (const float4*)y;

    __shared__ double  Sh[15];
    __shared__ GNState st;

    if (threadIdx.x == 0) {
        // u0 = inv_softplus(clip(x_init, 1e-3))
        for (int i = 0; i < 4; i++) {
            float xi = fmaxf(x_init[i], 1e-3f);
            st.ucand[i] = logf(expf(xi) - 1.0f + 1e-8f);
            st.du[i] = 0.0f;
        }
        st.first = 1; st.force = 0; st.trial = 0; st.iter = 0; st.done = 0;
        st.step = 0.0f; st.gd = 0.0f; st.loss = 0.0f;
    }
    __syncthreads();

    for (int pass = 0; pass < 400; pass++) {
        if (st.done) break;

        float uc[4], x[4];
#pragma unroll
        for (int i = 0; i < 4; i++) { uc[i] = st.ucand[i]; x[i] = sp_(uc[i]); }
        const float c0 = x[0], c1 = x[1], l0 = x[2], l1 = x[3];

        // ---- 15 sufficient statistics at the candidate point ----
        float s[15];
#pragma unroll
        for (int j = 0; j < 15; j++) s[j] = 0.0f;

        auto acc_pt = [&](float ti, float yi) {
            float e0 = __expf(-l0 * ti);
            float e1 = __expf(-l1 * ti);
            float r  = yi - __fmaf_rn(c1, e1, c0 * e0);
            float a2 = -c0 * ti * e0;
            float a3 = -c1 * ti * e1;
            s[0]  = __fmaf_rn(e0, e0, s[0]);
            s[1]  = __fmaf_rn(e0, e1, s[1]);
            s[2]  = __fmaf_rn(e0, a2, s[2]);
            s[3]  = __fmaf_rn(e0, a3, s[3]);
            s[4]  = __fmaf_rn(e1, e1, s[4]);
            s[5]  = __fmaf_rn(e1, a2, s[5]);
            s[6]  = __fmaf_rn(e1, a3, s[6]);
            s[7]  = __fmaf_rn(a2, a2, s[7]);
            s[8]  = __fmaf_rn(a2, a3, s[8]);
            s[9]  = __fmaf_rn(a3, a3, s[9]);
            s[10] = __fmaf_rn(e0, r,  s[10]);
            s[11] = __fmaf_rn(e1, r,  s[11]);
            s[12] = __fmaf_rn(a2, r,  s[12]);
            s[13] = __fmaf_rn(a3, r,  s[13]);
            s[14] = __fmaf_rn(r,  r,  s[14]);
        };

        for (int i = gtid; i < n4; i += strd) {
            float4 tv = t4[i], yv = y4[i];
            acc_pt(tv.x, yv.x); acc_pt(tv.y, yv.y);
            acc_pt(tv.z, yv.z); acc_pt(tv.w, yv.w);
        }
        for (int i = (n4 << 2) + gtid; i < n; i += strd)
            acc_pt(t[i], y[i]);

        block_reduce_store(s);
        grid_sync(nb);
        cross_reduce(Sh, nb);

        // ---- fused Armijo test + GN solve (thread 0; identical per block) --
        if (threadIdx.x == 0) {
            float loss_c = (float)Sh[14] + mu * dot4(x);
            bool acc = st.first || st.force ||
                       (loss_c <= st.loss - 1e-4f * st.step * st.gd);
            if (acc) {
                // movement & decrease of the step just taken
                float nn = ((st.du[0]*st.du[0] + st.du[1]*st.du[1])
                            + st.du[2]*st.du[2]) + st.du[3]*st.du[3];
                float upd = st.step * sqrtf(nn);
                float dec = st.loss - loss_c;
                bool stop = !st.first &&
                            ((upd < 1e-6f) ||
                             (dec < 1e-5f * fabsf(loss_c)) ||
                             (st.iter >= 300));
                for (int i = 0; i < 4; i++) st.uacc[i] = uc[i];
                st.loss = loss_c;
                st.iter++;
                if (stop) {
                    st.done = 1;
                } else {
                    // new GN direction from this pass's stats
                    const int sym[4][4] = {{0,1,2,3},{1,4,5,6},{2,5,7,8},{3,6,8,9}};
                    float sd[4];
                    for (int i = 0; i < 4; i++) sd[i] = 1.0f / (1.0f + __expf(-uc[i]));
                    double H[4][4];
                    float  grad[4];
                    for (int i = 0; i < 4; i++) {
                        for (int j = 0; j < 4; j++)
                            H[i][j] = Sh[sym[i][j]] * (double)sd[i] * (double)sd[j];
                        H[i][i] += (double)(mu + 1e-7f);
                        grad[i] = -(sd[i] * (float)Sh[10 + i]) + mu * x[i] * sd[i];
                    }
                    double bb[4], dud[4];
                    for (int i = 0; i < 4; i++) bb[i] = -(double)grad[i];
                    solve4(H, bb, dud);
                    float gd = 0.0f;
                    for (int i = 0; i < 4; i++) {
                        st.du[i] = (float)dud[i];
                        gd += grad[i] * st.du[i];
                    }
                    st.gd    = gd;
                    st.step  = 1.0f;
                    st.trial = 0;
                    st.first = 0;
                    st.force = 0;
                    for (int i = 0; i < 4; i++)
                        st.ucand[i] = uc[i] + st.du[i];
                }
            } else {
                // reject: halve the step, retry from the accepted point
                st.trial++;
                st.step *= 0.5f;
                if (st.trial >= 25) st.force = 1;  // ref: take the halved step
                for (int i = 0; i < 4; i++)
                    st.ucand[i] = st.uacc[i] + st.step * st.du[i];
            }
        }
        __syncthreads();
    }

    if (blockIdx.x == 0 && threadIdx.x == 0) {
        for (int i = 0; i < 4; i++) out[i] = sp_(st.uacc[i]);
    }
}

extern "C" void kernel_launch(void* const* d_in, const int* in_sizes, int n_in,
                              void* d_out, int out_size) {
    const float* logmu  = (const float*)d_in[0];
    const float* y      = (const float*)d_in[1];
    const float* t      = (const float*)d_in[2];
    const float* x_init = (const float*)d_in[3];
    float* out = (float*)d_out;
    int n = in_sizes[1];

    int dev = 0;
    cudaGetDevice(&dev);
    int sms = 0;
    cudaDeviceGetAttribute(&sms, cudaDevAttrMultiProcessorCount, dev);
    if (sms <= 0) sms = 148;

    // Deadlock-safe grid for the software barrier: only launch as many
    // blocks/SM as are guaranteed co-resident (capped at 2).
    int bpsm = 1;
    cudaOccupancyMaxActiveBlocksPerMultiprocessor(&bpsm, gn_kernel, NTHR, 0);
    if (bpsm < 1) bpsm = 1;
    if (bpsm > 2) bpsm = 2;

    int nb = sms * bpsm;
    if (nb > MAXB) nb = MAXB;

    gn_kernel<<<nb, NTHR>>>(logmu, y, t, x_init, out, n, nb);
}

// round 14
// speedup vs baseline: 375.1683x; 2.5570x over previous
#include <cuda_runtime.h>
#include <math.h>

// ---------------------------------------------------------------------------
// Persistent single-kernel Gauss-Newton solver for the bi-exponential fit.
// R14: one pass per GN iteration (fused Armijo, from R13) +
//  - acquire/release grid barrier (no MEMBAR.ALL, no nanosleep)
//  - float Cholesky solve (SPD H; FFMA chain instead of DFMA chain)
//  - transposed + parity double-buffered partials (coalesced cross-reduce,
//    closes the WAR window between a fast block's next-pass store and a slow
//    block's current-pass read)
//  - 152 blocks x 1024 threads (fewer barrier participants, same total work)
// ---------------------------------------------------------------------------

#define MAXB 384
#define NTHR 1024
#define NW   (NTHR / 32)

// ---- cross-block state ----------------------------------------------------
__device__ unsigned        g_bar_cnt = 0;
__device__ unsigned        g_bar_gen = 0;
__device__ volatile float  g_part[2][16][MAXB];   // [pass parity][stat][block]

// ---- acquire/release software grid barrier --------------------------------
__device__ __forceinline__ void grid_sync(int nb) {
    __syncthreads();
    if (threadIdx.x == 0) {
        unsigned gen;
        asm volatile("ld.relaxed.gpu.u32 %0, [%1];"
                     : "=r"(gen) : "l"(&g_bar_gen) : "memory");
        unsigned ticket;
        asm volatile("atom.acq_rel.gpu.add.u32 %0, [%1], %2;"
                     : "=r"(ticket) : "l"(&g_bar_cnt), "r"(1u) : "memory");
        if (ticket == (unsigned)(nb - 1)) {
            asm volatile("st.relaxed.gpu.u32 [%0], %1;"
                         :: "l"(&g_bar_cnt), "r"(0u) : "memory");
            asm volatile("st.release.gpu.u32 [%0], %1;"
                         :: "l"(&g_bar_gen), "r"(gen + 1u) : "memory");
        } else {
            unsigned cur;
            do {
                asm volatile("ld.acquire.gpu.u32 %0, [%1];"
                             : "=r"(cur) : "l"(&g_bar_gen) : "memory");
            } while (cur == gen);
        }
    }
    __syncthreads();
}

__device__ __forceinline__ float warp_sum(float v) {
#pragma unroll
    for (int o = 16; o > 0; o >>= 1) v += __shfl_down_sync(0xffffffffu, v, o);
    return v;
}

__device__ __forceinline__ double warp_sum_d(double v) {
#pragma unroll
    for (int o = 16; o > 0; o >>= 1) v += __shfl_down_sync(0xffffffffu, v, o);
    return v;
}

// Deterministic block reduction of 15 partials -> g_part[par][j][blockIdx.x]
__device__ __forceinline__ void block_reduce_store(const float* s, int par) {
    __shared__ float red[15][NW];
    int lane = threadIdx.x & 31, w = threadIdx.x >> 5;
#pragma unroll
    for (int j = 0; j < 15; j++) {
        float v = warp_sum(s[j]);
        if (lane == 0) red[j][w] = v;
    }
    __syncthreads();
    if (w == 0) {
#pragma unroll
        for (int j = 0; j < 15; j++) {
            float v = warp_sum(red[j][lane]);   // NW == 32
            if (lane == 0) g_part[par][j][blockIdx.x] = v;
        }
    }
    __syncthreads();
}

// Every block reduces all per-block partials itself (bit-identical across
// blocks). Transposed layout -> coalesced: warp w reads consecutive blocks.
__device__ __forceinline__ void cross_reduce(double* Sh, int nb, int par) {
    int lane = threadIdx.x & 31, w = threadIdx.x >> 5;
    if (w < 15) {
        double a = 0.0;
        for (int b = lane; b < nb; b += 32) a += (double)g_part[par][w][b];
        a = warp_sum_d(a);
        if (lane == 0) Sh[w] = a;
    }
    __syncthreads();
}

// softplus with the SAME exp everywhere -> bitwise-stable plateau behavior
__device__ __forceinline__ float sp_(float u) { return log1pf(__expf(u)); }

__device__ __forceinline__ float dot4(const float* a) {
    return ((a[0] * a[0] + a[1] * a[1]) + a[2] * a[2]) + a[3] * a[3];
}

// 4x4 SPD solve via float Cholesky (no pivoting needed: H = J^T J + mu I).
__device__ __forceinline__ void chol_solve4(const float A[4][4],
                                            const float b[4], float x[4]) {
    float L[4][4];
#pragma unroll
    for (int k = 0; k < 4; k++) {
        float d = A[k][k];
#pragma unroll
        for (int j = 0; j < 4; j++) if (j < k) d -= L[k][j] * L[k][j];
        float lkk = sqrtf(d);
        L[k][k] = lkk;
        float inv = __fdividef(1.0f, lkk);
#pragma unroll
        for (int i = 0; i < 4; i++) if (i > k) {
            float s2 = A[i][k];
#pragma unroll
            for (int j = 0; j < 4; j++) if (j < k) s2 -= L[i][j] * L[k][j];
            L[i][k] = s2 * inv;
        }
    }
    float z[4];
#pragma unroll
    for (int i = 0; i < 4; i++) {
        float s2 = b[i];
#pragma unroll
        for (int j = 0; j < 4; j++) if (j < i) s2 -= L[i][j] * z[j];
        z[i] = __fdividef(s2, L[i][i]);
    }
#pragma unroll
    for (int i = 3; i >= 0; i--) {
        float s2 = z[i];
#pragma unroll
        for (int j = 0; j < 4; j++) if (j > i) s2 -= L[j][i] * x[j];
        x[i] = __fdividef(s2, L[i][i]);
    }
}

// Per-block solver state (identical contents in every block).
struct GNState {
    float ucand[4];   // point evaluated by the NEXT pass
    float uacc[4];    // last accepted point
    float du[4];      // current search direction (from uacc)
    float gd;         // grad . du at uacc
    float loss;       // accepted loss
    float step;       // step size for current candidate
    int   first;      // no accepted point yet
    int   force;      // 25 halvings exhausted -> accept unconditionally
    int   trial;      // halvings this iteration
    int   iter;       // accepted GN iterations
    int   done;
};

__global__ void __launch_bounds__(NTHR, 1)
gn_kernel(const float* __restrict__ logmu_p,
          const float* __restrict__ y,
          const float* __restrict__ t,
          const float* __restrict__ x_init,
          float* __restrict__ out, int n, int nb) {
    const float mu   = expf(logmu_p[0]);
    const int   gtid = blockIdx.x * NTHR + threadIdx.x;
    const int   strd = nb * NTHR;
    const int   n4   = n >> 2;
    const float4* __restrict__ t4 = (const float4*)t;
    const float4* __restrict__ y4 = (const float4*)y;

    __shared__ double  Sh[15];
    __shared__ GNState st;

    if (threadIdx.x == 0) {
        // u0 = inv_softplus(clip(x_init, 1e-3))
        for (int i = 0; i < 4; i++) {
            float xi = fmaxf(x_init[i], 1e-3f);
            st.ucand[i] = logf(expf(xi) - 1.0f + 1e-8f);
            st.du[i] = 0.0f;
        }
        st.first = 1; st.force = 0; st.trial = 0; st.iter = 0; st.done = 0;
        st.step = 0.0f; st.gd = 0.0f; st.loss = 0.0f;
    }
    __syncthreads();

    for (int pass = 0; pass < 400; pass++) {
        if (st.done) break;
        const int par = pass & 1;

        float uc[4], x[4];
#pragma unroll
        for (int i = 0; i < 4; i++) { uc[i] = st.ucand[i]; x[i] = sp_(uc[i]); }
        const float c0 = x[0], c1 = x[1], l0 = x[2], l1 = x[3];

        // ---- 15 sufficient statistics at the candidate point ----
        float s[15];
#pragma unroll
        for (int j = 0; j < 15; j++) s[j] = 0.0f;

        auto acc_pt = [&](float ti, float yi) {
            float e0 = __expf(-l0 * ti);
            float e1 = __expf(-l1 * ti);
            float r  = yi - __fmaf_rn(c1, e1, c0 * e0);
            float a2 = -c0 * ti * e0;
            float a3 = -c1 * ti * e1;
            s[0]  = __fmaf_rn(e0, e0, s[0]);
            s[1]  = __fmaf_rn(e0, e1, s[1]);
            s[2]  = __fmaf_rn(e0, a2, s[2]);
            s[3]  = __fmaf_rn(e0, a3, s[3]);
            s[4]  = __fmaf_rn(e1, e1, s[4]);
            s[5]  = __fmaf_rn(e1, a2, s[5]);
            s[6]  = __fmaf_rn(e1, a3, s[6]);
            s[7]  = __fmaf_rn(a2, a2, s[7]);
            s[8]  = __fmaf_rn(a2, a3, s[8]);
            s[9]  = __fmaf_rn(a3, a3, s[9]);
            s[10] = __fmaf_rn(e0, r,  s[10]);
            s[11] = __fmaf_rn(e1, r,  s[11]);
            s[12] = __fmaf_rn(a2, r,  s[12]);
            s[13] = __fmaf_rn(a3, r,  s[13]);
            s[14] = __fmaf_rn(r,  r,  s[14]);
        };

        for (int i = gtid; i < n4; i += strd) {
            float4 tv = t4[i], yv = y4[i];
            acc_pt(tv.x, yv.x); acc_pt(tv.y, yv.y);
            acc_pt(tv.z, yv.z); acc_pt(tv.w, yv.w);
        }
        for (int i = (n4 << 2) + gtid; i < n; i += strd)
            acc_pt(t[i], y[i]);

        block_reduce_store(s, par);
        grid_sync(nb);
        cross_reduce(Sh, nb, par);

        // ---- fused Armijo test + GN solve (thread 0; identical per block) --
        if (threadIdx.x == 0) {
            float loss_c = (float)Sh[14] + mu * dot4(x);
            bool acc = st.first || st.force ||
                       (loss_c <= st.loss - 1e-4f * st.step * st.gd);
            if (acc) {
                float nn = ((st.du[0]*st.du[0] + st.du[1]*st.du[1])
                            + st.du[2]*st.du[2]) + st.du[3]*st.du[3];
                float upd = st.step * sqrtf(nn);
                float dec = st.loss - loss_c;
                bool stop = !st.first &&
                            ((upd < 1e-5f) ||
                             (dec < 1e-4f * fabsf(loss_c)) ||
                             (st.iter >= 300));
                for (int i = 0; i < 4; i++) st.uacc[i] = uc[i];
                st.loss = loss_c;
                st.iter++;
                if (stop) {
                    st.done = 1;
                } else {
                    const int sym[4][4] = {{0,1,2,3},{1,4,5,6},{2,5,7,8},{3,6,8,9}};
                    float sd[4];
                    for (int i = 0; i < 4; i++) sd[i] = 1.0f / (1.0f + __expf(-uc[i]));
                    float H[4][4], grad[4], rhs[4], du[4];
                    for (int i = 0; i < 4; i++) {
                        for (int j = 0; j < 4; j++)
                            H[i][j] = (float)Sh[sym[i][j]] * sd[i] * sd[j];
                        H[i][i] += mu + 1e-7f;
                        grad[i] = -(sd[i] * (float)Sh[10 + i]) + mu * x[i] * sd[i];
                        rhs[i]  = -grad[i];
                    }
                    chol_solve4(H, rhs, du);
                    float gd = 0.0f;
                    for (int i = 0; i < 4; i++) {
                        st.du[i] = du[i];
                        gd += grad[i] * du[i];
                    }
                    st.gd    = gd;
                    st.step  = 1.0f;
                    st.trial = 0;
                    st.first = 0;
                    st.force = 0;
                    for (int i = 0; i < 4; i++)
                        st.ucand[i] = uc[i] + du[i];
                }
            } else {
                // reject: halve the step, retry from the accepted point
                st.trial++;
                st.step *= 0.5f;
                if (st.trial >= 25) st.force = 1;  // ref: take the halved step
                for (int i = 0; i < 4; i++)
                    st.ucand[i] = st.uacc[i] + st.step * st.du[i];
            }
        }
        __syncthreads();
    }

    if (blockIdx.x == 0 && threadIdx.x == 0) {
        for (int i = 0; i < 4; i++) out[i] = sp_(st.uacc[i]);
    }
}

extern "C" void kernel_launch(void* const* d_in, const int* in_sizes, int n_in,
                              void* d_out, int out_size) {
    const float* logmu  = (const float*)d_in[0];
    const float* y      = (const float*)d_in[1];
    const float* t      = (const float*)d_in[2];
    const float* x_init = (const float*)d_in[3];
    float* out = (float*)d_out;
    int n = in_sizes[1];

    int dev = 0;
    cudaGetDevice(&dev);
    int sms = 0;
    cudaDeviceGetAttribute(&sms, cudaDevAttrMultiProcessorCount, dev);
    if (sms <= 0) sms = 148;

    // Deadlock-safe grid for the software barrier: only launch as many
    // blocks/SM as are guaranteed co-resident.
    int bpsm = 1;
    cudaOccupancyMaxActiveBlocksPerMultiprocessor(&bpsm, gn_kernel, NTHR, 0);
    if (bpsm < 1) bpsm = 1;
    if (bpsm > 2) bpsm = 2;

    int nb = sms * bpsm;
    if (nb > MAXB) nb = MAXB;

    gn_kernel<<<nb, NTHR>>>(logmu, y, t, x_init, out, n, nb);
}